// round 1
// baseline (speedup 1.0000x reference)
#include <cuda_runtime.h>
#include <cuda_bf16.h>

// Problem shape (fixed by the dataset): x:(B=16, D=1024), alphas/betas:(1, H=4)
#define D_DIM 1024
#define H_DIM 4
#define EPSILON 1e-8f
#define THREADS 256
#define QPB 2                 // queries per block (8 warps = QPB * H_DIM work items)
#define KPL (D_DIM / 32)      // keys per lane = 32

__global__ __launch_bounds__(THREADS)
void flatt_kernel(const float* __restrict__ x,
                  const float* __restrict__ aq, const float* __restrict__ bq,
                  const float* __restrict__ ak, const float* __restrict__ bk,
                  const float* __restrict__ av, const float* __restrict__ bv,
                  float* __restrict__ out)
{
    __shared__ float sx[D_DIM];
    __shared__ float sk[H_DIM][D_DIM];
    __shared__ float sv[H_DIM][D_DIM];
    __shared__ float satt[QPB][H_DIM];

    const int blocks_per_batch = D_DIM / QPB;
    const int b  = blockIdx.x / blocks_per_batch;
    const int i0 = (blockIdx.x % blocks_per_batch) * QPB;
    const float* xb = x + b * D_DIM;

    // Stage x row; compute per-head k, v arrays once for the whole block.
    float cak[H_DIM], cbk[H_DIM], cav[H_DIM], cbv[H_DIM];
#pragma unroll
    for (int h = 0; h < H_DIM; h++) {
        cak[h] = ak[h]; cbk[h] = bk[h];
        cav[h] = av[h]; cbv[h] = bv[h];
    }
    for (int j = threadIdx.x; j < D_DIM; j += THREADS) {
        float xv = xb[j];
        sx[j] = xv;
#pragma unroll
        for (int h = 0; h < H_DIM; h++) {
            sk[h][j] = fmaf(cak[h], xv, cbk[h]);
            sv[h][j] = fmaf(cav[h], xv, cbv[h]);
        }
    }
    __syncthreads();

    const int warp = threadIdx.x >> 5;
    const int lane = threadIdx.x & 31;
    const int qloc = warp >> 2;        // 0..QPB-1
    const int qi   = i0 + qloc;        // query index within row
    const int h    = warp & 3;         // head

    // q scalar for this (query, head)
    const float q = fmaf(aq[h], sx[qi], bq[h]);

    // ---- Pass 1: scores s_j = 1/(|k_j - q| + eps), track max ----
    float s[KPL];
    float m = -1e30f;
#pragma unroll
    for (int t = 0; t < KPL; t++) {
        int j = t * 32 + lane;
        float d = fabsf(sk[h][j] - q) + EPSILON;
        float sc = __frcp_rn(d);       // correctly-rounded: matches JAX division
        s[t] = sc;
        m = fmaxf(m, sc);
    }
#pragma unroll
    for (int o = 16; o; o >>= 1)
        m = fmaxf(m, __shfl_xor_sync(0xffffffffu, m, o));

    // ---- Pass 2: p = exp(s - m); accumulate sum(p) and sum(p*v) ----
    float psum = 0.f, acc = 0.f;
#pragma unroll
    for (int t = 0; t < KPL; t++) {
        int j = t * 32 + lane;
        float p = __expf(s[t] - m);
        psum += p;
        acc = fmaf(p, sv[h][j], acc);
    }
#pragma unroll
    for (int o = 16; o; o >>= 1) {
        psum += __shfl_xor_sync(0xffffffffu, psum, o);
        acc  += __shfl_xor_sync(0xffffffffu, acc,  o);
    }

    if (lane == 0)
        satt[qloc][h] = (acc / psum) * 0.5f;   // 1/sqrt(H)=0.5 folded here
    __syncthreads();

    // Combine heads + residual, one thread per query
    if (threadIdx.x < QPB) {
        int qq = i0 + threadIdx.x;
        float r = sx[qq];
#pragma unroll
        for (int h2 = 0; h2 < H_DIM; h2++) r += satt[threadIdx.x][h2];
        out[b * D_DIM + qq] = r;
    }
}

extern "C" void kernel_launch(void* const* d_in, const int* in_sizes, int n_in,
                              void* d_out, int out_size)
{
    const float* x  = (const float*)d_in[0];
    const float* aq = (const float*)d_in[1];
    const float* bq = (const float*)d_in[2];
    const float* ak = (const float*)d_in[3];
    const float* bk = (const float*)d_in[4];
    const float* av = (const float*)d_in[5];
    const float* bv = (const float*)d_in[6];
    float* out = (float*)d_out;

    const int B = in_sizes[0] / D_DIM;     // 16
    const int grid = B * (D_DIM / QPB);    // 8192 blocks

    flatt_kernel<<<grid, THREADS>>>(x, aq, bq, ak, bk, av, bv, out);
}

// round 2
// speedup vs baseline: 1.2764x; 1.2764x over previous
#include <cuda_runtime.h>
#include <cuda_bf16.h>

// Problem shape (fixed by the dataset): x:(B=16, D=1024), alphas/betas:(1, H=4)
#define D_DIM 1024
#define H_DIM 4
#define EPSILON 1e-8f
#define THREADS 256
#define QPB 2                 // queries per block (8 warps = QPB * H_DIM work items)
#define NT4 8                 // float4 tiles per lane (8 * 4 = 32 keys per lane)
#define LOG2E 1.4426950408889634f

// rcp.approx + one Newton step: rel err ~2^-44, 3 instructions total.
__device__ __forceinline__ float frcp_fast(float d) {
    float r;
    asm("rcp.approx.f32 %0, %1;" : "=f"(r) : "f"(d));
    float e = __fmaf_rn(-d, r, 1.0f);
    return __fmaf_rn(r, e, r);
}

// Bare EX2 (argument is already base-2).
__device__ __forceinline__ float ex2_fast(float a) {
    float r;
    asm("ex2.approx.f32 %0, %1;" : "=f"(r) : "f"(a));
    return r;
}

__global__ __launch_bounds__(THREADS)
void flatt_kernel(const float* __restrict__ x,
                  const float* __restrict__ aq, const float* __restrict__ bq,
                  const float* __restrict__ ak, const float* __restrict__ bk,
                  const float* __restrict__ av, const float* __restrict__ bv,
                  float* __restrict__ out)
{
    __shared__ float4 sk4[H_DIM][D_DIM / 4];
    __shared__ float4 sv4[H_DIM][D_DIM / 4];
    __shared__ float  sx[D_DIM];
    __shared__ float  satt[QPB][H_DIM];

    const int blocks_per_batch = D_DIM / QPB;
    const int b  = blockIdx.x / blocks_per_batch;
    const int i0 = (blockIdx.x % blocks_per_batch) * QPB;

    // ---- Stage x and per-head k,v (vectorized: 1 float4 per thread) ----
    {
        const float4 xv = ((const float4*)(x + b * D_DIM))[threadIdx.x];
        ((float4*)sx)[threadIdx.x] = xv;
#pragma unroll
        for (int h = 0; h < H_DIM; h++) {
            const float a1 = ak[h], b1 = bk[h];
            sk4[h][threadIdx.x] = make_float4(fmaf(a1, xv.x, b1), fmaf(a1, xv.y, b1),
                                              fmaf(a1, xv.z, b1), fmaf(a1, xv.w, b1));
            const float a2 = av[h], b2 = bv[h];
            sv4[h][threadIdx.x] = make_float4(fmaf(a2, xv.x, b2), fmaf(a2, xv.y, b2),
                                              fmaf(a2, xv.z, b2), fmaf(a2, xv.w, b2));
        }
    }
    __syncthreads();

    const int warp = threadIdx.x >> 5;
    const int lane = threadIdx.x & 31;
    const int qloc = warp >> 2;        // 0..QPB-1
    const int qi   = i0 + qloc;        // query index within row
    const int h    = warp & 3;         // head

    const float q = fmaf(aq[h], sx[qi], bq[h]);

    // ---- Pass 1: s_j = 1/(|k_j - q| + eps), track max ----
    float s[NT4 * 4];
    float m0 = -1e30f, m1 = -1e30f, m2 = -1e30f, m3 = -1e30f;
#pragma unroll
    for (int t = 0; t < NT4; t++) {
        const float4 kk = sk4[h][t * 32 + lane];
        float d0 = fabsf(kk.x - q) + EPSILON;
        float d1 = fabsf(kk.y - q) + EPSILON;
        float d2 = fabsf(kk.z - q) + EPSILON;
        float d3 = fabsf(kk.w - q) + EPSILON;
        float s0 = frcp_fast(d0), s1 = frcp_fast(d1);
        float s2 = frcp_fast(d2), s3 = frcp_fast(d3);
        s[t * 4 + 0] = s0; s[t * 4 + 1] = s1;
        s[t * 4 + 2] = s2; s[t * 4 + 3] = s3;
        m0 = fmaxf(m0, s0); m1 = fmaxf(m1, s1);
        m2 = fmaxf(m2, s2); m3 = fmaxf(m3, s3);
    }
    float m = fmaxf(fmaxf(m0, m1), fmaxf(m2, m3));
#pragma unroll
    for (int o = 16; o; o >>= 1)
        m = fmaxf(m, __shfl_xor_sync(0xffffffffu, m, o));

    // ---- Pass 2: p = exp2(s*log2e - m*log2e); accumulate ----
    const float c = -m * LOG2E;
    float ps0 = 0.f, ps1 = 0.f, ps2 = 0.f, ps3 = 0.f;
    float ac0 = 0.f, ac1 = 0.f, ac2 = 0.f, ac3 = 0.f;
#pragma unroll
    for (int t = 0; t < NT4; t++) {
        const float4 vv = sv4[h][t * 32 + lane];
        float p0 = ex2_fast(fmaf(s[t * 4 + 0], LOG2E, c));
        float p1 = ex2_fast(fmaf(s[t * 4 + 1], LOG2E, c));
        float p2 = ex2_fast(fmaf(s[t * 4 + 2], LOG2E, c));
        float p3 = ex2_fast(fmaf(s[t * 4 + 3], LOG2E, c));
        ps0 += p0; ps1 += p1; ps2 += p2; ps3 += p3;
        ac0 = fmaf(p0, vv.x, ac0);
        ac1 = fmaf(p1, vv.y, ac1);
        ac2 = fmaf(p2, vv.z, ac2);
        ac3 = fmaf(p3, vv.w, ac3);
    }
    float psum = (ps0 + ps1) + (ps2 + ps3);
    float acc  = (ac0 + ac1) + (ac2 + ac3);
#pragma unroll
    for (int o = 16; o; o >>= 1) {
        psum += __shfl_xor_sync(0xffffffffu, psum, o);
        acc  += __shfl_xor_sync(0xffffffffu, acc,  o);
    }

    if (lane == 0)
        satt[qloc][h] = (acc / psum) * 0.5f;   // 1/sqrt(H)=0.5 folded here
    __syncthreads();

    // Combine heads + residual, one thread per query
    if (threadIdx.x < QPB) {
        int qq = i0 + threadIdx.x;
        float r = sx[qq];
#pragma unroll
        for (int h2 = 0; h2 < H_DIM; h2++) r += satt[threadIdx.x][h2];
        out[b * D_DIM + qq] = r;
    }
}

extern "C" void kernel_launch(void* const* d_in, const int* in_sizes, int n_in,
                              void* d_out, int out_size)
{
    const float* x  = (const float*)d_in[0];
    const float* aq = (const float*)d_in[1];
    const float* bq = (const float*)d_in[2];
    const float* ak = (const float*)d_in[3];
    const float* bk = (const float*)d_in[4];
    const float* av = (const float*)d_in[5];
    const float* bv = (const float*)d_in[6];
    float* out = (float*)d_out;

    const int B = in_sizes[0] / D_DIM;     // 16
    const int grid = B * (D_DIM / QPB);    // 8192 blocks

    flatt_kernel<<<grid, THREADS>>>(x, aq, bq, ak, bk, av, bv, out);
}

// round 3
// speedup vs baseline: 1.6446x; 1.2885x over previous
#include <cuda_runtime.h>
#include <cuda_bf16.h>

// Problem shape (fixed by the dataset): x:(B=16, D=1024), alphas/betas:(1, H=4)
#define D_DIM 1024
#define H_DIM 4
#define EPSILON 1e-8f
#define THREADS 256
#define QPB 2                 // queries per block (8 warps = QPB * H_DIM work items)
#define NT 8                  // float4 tiles per lane (8 * 4 = 32 keys per lane)
#define LOG2E 1.4426950408889634f

// rcp.approx + one Newton step: rel err ~2^-44, 3 instructions total.
__device__ __forceinline__ float frcp_fast(float d) {
    float r;
    asm("rcp.approx.f32 %0, %1;" : "=f"(r) : "f"(d));
    float e = __fmaf_rn(-d, r, 1.0f);
    return __fmaf_rn(r, e, r);
}

__device__ __forceinline__ float ex2_fast(float a) {
    float r;
    asm("ex2.approx.f32 %0, %1;" : "=f"(r) : "f"(a));
    return r;
}

__global__ __launch_bounds__(THREADS)
void flatt_kernel(const float* __restrict__ x,
                  const float* __restrict__ aq, const float* __restrict__ bq,
                  const float* __restrict__ ak, const float* __restrict__ bk,
                  const float* __restrict__ av, const float* __restrict__ bv,
                  float* __restrict__ out)
{
    __shared__ float4 sk4[H_DIM][D_DIM / 4];
    __shared__ float4 sv4[H_DIM][D_DIM / 4];
    __shared__ float  sx[D_DIM];
    __shared__ float  satt[QPB][H_DIM];

    const int blocks_per_batch = D_DIM / QPB;
    const int b  = blockIdx.x / blocks_per_batch;
    const int i0 = (blockIdx.x % blocks_per_batch) * QPB;

    // ---- Stage x and per-head k,v (vectorized: 1 float4 per thread) ----
    {
        const float4 xv = ((const float4*)(x + b * D_DIM))[threadIdx.x];
        ((float4*)sx)[threadIdx.x] = xv;
#pragma unroll
        for (int h = 0; h < H_DIM; h++) {
            const float a1 = ak[h], b1 = bk[h];
            sk4[h][threadIdx.x] = make_float4(fmaf(a1, xv.x, b1), fmaf(a1, xv.y, b1),
                                              fmaf(a1, xv.z, b1), fmaf(a1, xv.w, b1));
            const float a2 = av[h], b2 = bv[h];
            sv4[h][threadIdx.x] = make_float4(fmaf(a2, xv.x, b2), fmaf(a2, xv.y, b2),
                                              fmaf(a2, xv.z, b2), fmaf(a2, xv.w, b2));
        }
    }
    __syncthreads();

    const int warp = threadIdx.x >> 5;
    const int lane = threadIdx.x & 31;
    const int qloc = warp >> 2;        // 0..QPB-1
    const int qi   = i0 + qloc;        // query index within row
    const int h    = warp & 3;         // head

    const float q = fmaf(aq[h], sx[qi], bq[h]);

    // ---- Pass 1: distances d_j = |k_j - q| + eps; per-tile and global min ----
    float d[NT * 4];
    float dt[NT];                      // per-lane, per-tile min distance
#pragma unroll
    for (int t = 0; t < NT; t++) {
        const float4 kk = sk4[h][t * 32 + lane];
        float d0 = fabsf(kk.x - q) + EPSILON;
        float d1 = fabsf(kk.y - q) + EPSILON;
        float d2 = fabsf(kk.z - q) + EPSILON;
        float d3 = fabsf(kk.w - q) + EPSILON;
        d[t * 4 + 0] = d0; d[t * 4 + 1] = d1;
        d[t * 4 + 2] = d2; d[t * 4 + 3] = d3;
        dt[t] = fminf(fminf(d0, d1), fminf(d2, d3));
    }
    float dmin = dt[0];
#pragma unroll
    for (int t = 1; t < NT; t++) dmin = fminf(dmin, dt[t]);
#pragma unroll
    for (int o = 16; o; o >>= 1)
        dmin = fminf(dmin, __shfl_xor_sync(0xffffffffu, dmin, o));

    // Max score (exact): softmax shift point. Terms with s < m - 80 contribute
    // < e^-115 ~ 1e-50 and are dropped. Liveness in d-space: d < 1/(m-80).
    const float m   = __frcp_rn(dmin);
    const float thr = (m > 81.0f) ? __frcp_rn(m - 80.0f) : 3.4e38f;
    const float c   = -m * LOG2E;

    // ---- Pass 2: only live tiles compute rcp/exp/accumulate ----
    float ps0 = 0.f, ps1 = 0.f, ac0 = 0.f, ac1 = 0.f;
#pragma unroll
    for (int t = 0; t < NT; t++) {
        if (__any_sync(0xffffffffu, dt[t] < thr)) {
            const float4 vv = sv4[h][t * 32 + lane];
            float s0 = frcp_fast(d[t * 4 + 0]);
            float s1 = frcp_fast(d[t * 4 + 1]);
            float s2 = frcp_fast(d[t * 4 + 2]);
            float s3 = frcp_fast(d[t * 4 + 3]);
            float p0 = ex2_fast(fmaf(s0, LOG2E, c));
            float p1 = ex2_fast(fmaf(s1, LOG2E, c));
            float p2 = ex2_fast(fmaf(s2, LOG2E, c));
            float p3 = ex2_fast(fmaf(s3, LOG2E, c));
            ps0 += p0 + p2;
            ps1 += p1 + p3;
            ac0 = fmaf(p0, vv.x, ac0);
            ac1 = fmaf(p1, vv.y, ac1);
            ac0 = fmaf(p2, vv.z, ac0);
            ac1 = fmaf(p3, vv.w, ac1);
        }
    }
    float psum = ps0 + ps1;
    float acc  = ac0 + ac1;
#pragma unroll
    for (int o = 16; o; o >>= 1) {
        psum += __shfl_xor_sync(0xffffffffu, psum, o);
        acc  += __shfl_xor_sync(0xffffffffu, acc,  o);
    }

    if (lane == 0)
        satt[qloc][h] = (acc / psum) * 0.5f;   // 1/sqrt(H)=0.5 folded here
    __syncthreads();

    // Combine heads + residual, one thread per query
    if (threadIdx.x < QPB) {
        int qq = i0 + threadIdx.x;
        float r = sx[qq];
#pragma unroll
        for (int h2 = 0; h2 < H_DIM; h2++) r += satt[threadIdx.x][h2];
        out[b * D_DIM + qq] = r;
    }
}

extern "C" void kernel_launch(void* const* d_in, const int* in_sizes, int n_in,
                              void* d_out, int out_size)
{
    const float* x  = (const float*)d_in[0];
    const float* aq = (const float*)d_in[1];
    const float* bq = (const float*)d_in[2];
    const float* ak = (const float*)d_in[3];
    const float* bk = (const float*)d_in[4];
    const float* av = (const float*)d_in[5];
    const float* bv = (const float*)d_in[6];
    float* out = (float*)d_out;

    const int B = in_sizes[0] / D_DIM;     // 16
    const int grid = B * (D_DIM / QPB);    // 8192 blocks

    flatt_kernel<<<grid, THREADS>>>(x, aq, bq, ak, bk, av, bv, out);
}